// round 17
// baseline (speedup 1.0000x reference)
#include <cuda_runtime.h>
#include <math.h>
#include <stdint.h>

#define NB   32      // batch
#define NT   4096    // sequence
#define NCAT 128
#define NNE  512
#define NHS  64

#define CHR  16                       // rows per chunk
#define CPB  8                        // chunks per block -> 128 rows/block
#define NBPB 32                       // blocks per batch (grid 1024, 1 wave)

// ---- scratch (device globals; no allocations allowed) ----
__device__ float g_qk[NB * NNE];
__device__ float g_pm[NB * NBPB];
__device__ float g_ps[NB * NBPB];
__device__ float g_pacc[(size_t)NB * NBPB * NNE];  // 2 MB
__device__ float g_y[NB * NNE];

// ============================================================
// Kernel A: q = cat_emb@Wq ; qk[n] = 0.125 * Wk[n,:]·q
// ============================================================
__global__ void kA(const float* __restrict__ cat_emb,
                   const float* __restrict__ Wq,
                   const float* __restrict__ Wk) {
    const int b = blockIdx.x;
    const int tid = threadIdx.x;
    const int h = tid & 63;
    const int part = tid >> 6;

    __shared__ float qpart[8][NHS];
    __shared__ float qs[NHS];

    float a = 0.f;
    const float* ce = cat_emb + b * NCAT;
    #pragma unroll
    for (int c = part * 16; c < part * 16 + 16; ++c)
        a += ce[c] * Wq[c * NHS + h];
    qpart[part][h] = a;
    __syncthreads();

    if (tid < NHS) {
        float q = 0.f;
        #pragma unroll
        for (int p = 0; p < 8; ++p) q += qpart[p][tid];
        qs[tid] = q * 0.125f;
    }
    __syncthreads();

    const float4* wk4 = reinterpret_cast<const float4*>(Wk + tid * NHS);
    const float4* q4  = reinterpret_cast<const float4*>(qs);
    float acc = 0.f;
    #pragma unroll
    for (int i = 0; i < 16; ++i) {
        const float4 w = wk4[i];
        const float4 qq = q4[i];
        acc += w.x * qq.x + w.y * qq.y + w.z * qq.z + w.w * qq.w;
    }
    g_qk[b * NNE + tid] = acc;
}

// ============================================================
// Fused kernel vC: cache-fused two-pass per chunk, plain LDG.
//  pass1 (kB pattern): warp-per-row float4 loads -> scores (warms L1/L2)
//  chunk softmax (R6 pattern) + running rescale (R10 pattern)
//  pass2 (kD pattern): thread-per-column scalar loads (cache hits)
// grid: (NBPB, NB) = 1024 blocks, 256 threads, tiny smem.
// ============================================================
__global__ void __launch_bounds__(256) kFuseC(const float* __restrict__ x) {
    const int b = blockIdx.y;
    const int blk = blockIdx.x;
    const int tid = threadIdx.x;
    const int warp = tid >> 5, lane = tid & 31;

    __shared__ float sscore[2][CHR];

    const float4* qkp = reinterpret_cast<const float4*>(g_qk + b * NNE);
    float4 qv[4];
    #pragma unroll
    for (int i = 0; i < 4; ++i) qv[i] = qkp[lane + 32 * i];

    const float* xb = x + ((size_t)b * NT + (size_t)blk * CHR * CPB) * NNE;

    float M = -INFINITY, S = 0.f, a0 = 0.f, a1 = 0.f;

    #pragma unroll
    for (int c = 0; c < CPB; ++c) {
        const float* xc = xb + (size_t)c * CHR * NNE;
        const int sb = c & 1;

        // ---- pass 1: scores, 2 rows per warp (kB pattern) ----
        #pragma unroll
        for (int j = 0; j < 2; ++j) {
            const int t = warp + 8 * j;
            const float4* xr = reinterpret_cast<const float4*>(
                xc + (size_t)t * NNE);
            float d = 0.f;
            #pragma unroll
            for (int i = 0; i < 4; ++i) {
                const float4 xv = xr[lane + 32 * i];
                d += xv.x * qv[i].x + xv.y * qv[i].y +
                     xv.z * qv[i].z + xv.w * qv[i].w;
            }
            #pragma unroll
            for (int o = 16; o > 0; o >>= 1)
                d += __shfl_xor_sync(0xffffffffu, d, o);
            if (lane == 0) sscore[sb][t] = d;
        }
        __syncthreads();   // only barrier per chunk (double-buffered scores)

        // ---- chunk softmax, redundantly in every warp (R6 pattern) ----
        const float s = sscore[sb][lane & 15];
        float mc = s;
        #pragma unroll
        for (int o = 8; o > 0; o >>= 1)
            mc = fmaxf(mc, __shfl_xor_sync(0xffffffffu, mc, o));
        const float newM = fmaxf(M, mc);
        const float f = __expf(M - newM);    // 0 on first chunk
        const float e = __expf(s - newM);
        float Ssum = e;
        #pragma unroll
        for (int o = 8; o > 0; o >>= 1)
            Ssum += __shfl_xor_sync(0xffffffffu, Ssum, o);
        S = S * f + Ssum;
        a0 *= f;
        a1 *= f;
        M = newM;

        // ---- pass 2: thread-per-column weighted sums (kD pattern; cache hits) ----
        #pragma unroll 4
        for (int t = 0; t < CHR; ++t) {
            const float wt = __shfl_sync(0xffffffffu, e, t);
            const float* row = xc + (size_t)t * NNE;
            a0 = fmaf(wt, __ldg(row + tid),       a0);
            a1 = fmaf(wt, __ldg(row + tid + 256), a1);
        }
    }

    float* p = g_pacc + (size_t)(b * NBPB + blk) * NNE;
    p[tid]       = a0;
    p[tid + 256] = a1;
    if (tid == 0) {
        g_pm[b * NBPB + blk] = M;
        g_ps[b * NBPB + blk] = S;
    }
}

// ============================================================
// Kernel E: combine 32 partials (8-way float4) -> xa; xa@Wv; @Wp; LayerNorm
// grid: NB, 1024 threads
// ============================================================
__global__ void kE(const float* __restrict__ Wv,
                   const float* __restrict__ Wp,
                   const float* __restrict__ gamma,
                   const float* __restrict__ beta) {
    const int b = blockIdx.x;
    const int tid = threadIdx.x;
    const int warp = tid >> 5, lane = tid & 31;

    __shared__ float spm[NBPB], sps[NBPB], sf[NBPB];
    __shared__ float4 xpart[8][NNE / 4];
    __shared__ float xa[NNE];
    __shared__ float wpart[16][NHS];
    __shared__ float outh[NHS];
    __shared__ float red[32];
    __shared__ float bcast;

    if (tid < NBPB) {
        spm[tid] = g_pm[b * NBPB + tid];
        sps[tid] = g_ps[b * NBPB + tid];
    }
    __syncthreads();

    float mb = -INFINITY;
    #pragma unroll
    for (int c = 0; c < NBPB; ++c) mb = fmaxf(mb, spm[c]);

    if (tid < NBPB) sf[tid] = __expf(spm[tid] - mb);
    __syncthreads();

    float Sb = 0.f;
    #pragma unroll
    for (int c = 0; c < NBPB; ++c) Sb += sps[c] * sf[c];

    {
        const int col4 = tid & 127;
        const int part = tid >> 7;        // 8 parts x 4 partials
        const float4* pp = reinterpret_cast<const float4*>(
            g_pacc + (size_t)(b * NBPB + part * 4) * NNE);
        const float* f = sf + part * 4;
        float4 a = make_float4(0.f, 0.f, 0.f, 0.f);
        #pragma unroll
        for (int c = 0; c < 4; ++c) {
            const float4 v = pp[(size_t)c * 128 + col4];
            const float fc = f[c];
            a.x = fmaf(v.x, fc, a.x);
            a.y = fmaf(v.y, fc, a.y);
            a.z = fmaf(v.z, fc, a.z);
            a.w = fmaf(v.w, fc, a.w);
        }
        xpart[part][col4] = a;
    }
    __syncthreads();
    if (tid < 128) {
        float4 a = xpart[0][tid];
        #pragma unroll
        for (int p = 1; p < 8; ++p) {
            const float4 v = xpart[p][tid];
            a.x += v.x; a.y += v.y; a.z += v.z; a.w += v.w;
        }
        const float inv = 1.f / Sb;
        reinterpret_cast<float4*>(xa)[tid] =
            make_float4(a.x * inv, a.y * inv, a.z * inv, a.w * inv);
    }
    __syncthreads();

    {
        const int h = tid & 63;
        const int part = tid >> 6;
        float po = 0.f;
        #pragma unroll
        for (int n = part * 32; n < part * 32 + 32; ++n)
            po = fmaf(xa[n], Wv[n * NHS + h], po);
        wpart[part][h] = po;
    }
    __syncthreads();
    if (tid < NHS) {
        float o = 0.f;
        #pragma unroll
        for (int p = 0; p < 16; ++p) o += wpart[p][tid];
        outh[tid] = o;
    }
    __syncthreads();

    float y = 0.f;
    if (tid < NNE) {
        #pragma unroll
        for (int h2 = 0; h2 < NHS; ++h2)
            y = fmaf(outh[h2], Wp[h2 * NNE + tid], y);
    }

    float s = (tid < NNE) ? y : 0.f;
    #pragma unroll
    for (int o = 16; o > 0; o >>= 1)
        s += __shfl_xor_sync(0xffffffffu, s, o);
    if (lane == 0) red[warp] = s;
    __syncthreads();
    if (tid < 32) {
        float ss2 = red[tid];
        #pragma unroll
        for (int o = 16; o > 0; o >>= 1)
            ss2 += __shfl_xor_sync(0xffffffffu, ss2, o);
        if (tid == 0) bcast = ss2;
    }
    __syncthreads();
    const float mu = bcast * (1.f / NNE);
    __syncthreads();

    const float d = (tid < NNE) ? (y - mu) : 0.f;
    float vs = d * d;
    #pragma unroll
    for (int o = 16; o > 0; o >>= 1)
        vs += __shfl_xor_sync(0xffffffffu, vs, o);
    if (lane == 0) red[warp] = vs;
    __syncthreads();
    if (tid < 32) {
        float ss2 = red[tid];
        #pragma unroll
        for (int o = 16; o > 0; o >>= 1)
            ss2 += __shfl_xor_sync(0xffffffffu, ss2, o);
        if (tid == 0) bcast = ss2;
    }
    __syncthreads();
    const float var = bcast * (1.f / NNE);
    const float rstd = rsqrtf(var + 1e-5f);

    if (tid < NNE)
        g_y[b * NNE + tid] = d * rstd * gamma[tid] + beta[tid];
}

// ============================================================
// Kernel F: broadcast g_y[b,:] to out[b, t, :]; streaming float4 stores
// ============================================================
#define ROWS_F 64
__global__ void kF(float* __restrict__ out) {
    const int b = blockIdx.y;
    const int tid = threadIdx.x;
    const int col = tid & 127;
    const int half = tid >> 7;

    const float4 val = reinterpret_cast<const float4*>(g_y + b * NNE)[col];

    const int t0 = blockIdx.x * ROWS_F;
    float4* o = reinterpret_cast<float4*>(out + ((size_t)b * NT + t0) * NNE);
    #pragma unroll 8
    for (int r = 0; r < ROWS_F / 2; ++r)
        __stcs(&o[(size_t)(r * 2 + half) * (NNE / 4) + col], val);
}

// ============================================================
extern "C" void kernel_launch(void* const* d_in, const int* in_sizes, int n_in,
                              void* d_out, int out_size) {
    const float* x       = (const float*)d_in[0];
    const float* cat_emb = (const float*)d_in[1];
    const float* Wq      = (const float*)d_in[2];
    const float* Wk      = (const float*)d_in[3];
    const float* Wv      = (const float*)d_in[4];
    const float* Wp      = (const float*)d_in[5];
    const float* gamma   = (const float*)d_in[6];
    const float* beta    = (const float*)d_in[7];
    float* out = (float*)d_out;

    kA<<<NB, 512>>>(cat_emb, Wq, Wk);
    kFuseC<<<dim3(NBPB, NB), 256>>>(x);
    kE<<<NB, 1024>>>(Wv, Wp, gamma, beta);
    kF<<<dim3(NT / ROWS_F, NB), 256>>>(out);
}